// round 8
// baseline (speedup 1.0000x reference)
#include <cuda_runtime.h>
#include <math.h>
#include <stdint.h>

#define VOCAB 50257
#define EDIM  256
#define HDIM  512
#define G3    1536
#define BATCH 64
#define LSEQ  64
#define SOS_TOK 2

// ---------------- persistent device state (no allocations allowed) ----------
__device__ float g_h[BATCH * HDIM];                    // current hidden state
__device__ float g_gi_part[4 * BATCH * G3];            // split-K partials (x @ W_ih^T)
__device__ float g_gh_part[4 * BATCH * G3];            // split-K partials (h @ W_hh^T)
__device__ unsigned long long g_amax[BATCH * 32];      // padded argmax slots (256B apart)

// ---------------------------------------------------------------------------
// Kernel 1: GRU input/hidden GEMMs, deterministic split-K (4 splits).
// grid = (48 j-tiles of 32, 4 splits), block = 128 threads.
// ---------------------------------------------------------------------------
__global__ __launch_bounds__(128) void gru_gemm_kernel(
    int s,
    const float* __restrict__ h0,
    const float* __restrict__ emb,
    const float* __restrict__ W_ih,
    const float* __restrict__ W_hh)
{
    __shared__ int   stok[BATCH];
    __shared__ float as_[64][65];   // [k][b]  (+1 pad: conflict-free)
    __shared__ float ws_[64][33];   // [k][j]  (+1 pad)

    const int tid   = threadIdx.x;
    const int jt    = blockIdx.x;     // 0..47
    const int split = blockIdx.y;     // 0..3
    const int j0    = jt * 32;
    const int tj    = tid & 7;        // j lane
    const int tb    = tid >> 3;       // b lane (0..15)

    if (tid < BATCH) {
        int t;
        if (s == 0) t = SOS_TOK;
        else        t = (int)(~(unsigned int)(g_amax[tid * 32] & 0xFFFFFFFFull));
        stok[tid] = t;
    }
    __syncthreads();

    const float* __restrict__ hprev = (s == 0) ? h0 : g_h;

    float acci[16], acch[16];
    #pragma unroll
    for (int i = 0; i < 16; i++) { acci[i] = 0.f; acch[i] = 0.f; }

    // ---------------- chunk 0: gi over x = emb[tok], K-range [split*64, +64)
    {
        const int k0 = split * 64;
        #pragma unroll
        for (int i = 0; i < 32; i++) {
            int idx = tid + 128 * i;
            int k = idx & 63, b = idx >> 6;
            as_[k][b] = emb[(size_t)stok[b] * EDIM + k0 + k];
        }
        #pragma unroll
        for (int i = 0; i < 16; i++) {
            int idx = tid + 128 * i;
            int k = idx & 63, j = idx >> 6;
            ws_[k][j] = W_ih[(size_t)(j0 + j) * EDIM + k0 + k];
        }
        __syncthreads();
        #pragma unroll 4
        for (int k = 0; k < 64; k++) {
            float a0 = as_[k][tb], a1 = as_[k][tb + 16], a2 = as_[k][tb + 32], a3 = as_[k][tb + 48];
            #pragma unroll
            for (int ji = 0; ji < 4; ji++) {
                float w = ws_[k][tj + 8 * ji];
                acci[ji * 4 + 0] += w * a0;
                acci[ji * 4 + 1] += w * a1;
                acci[ji * 4 + 2] += w * a2;
                acci[ji * 4 + 3] += w * a3;
            }
        }
        __syncthreads();
    }

    // ---------------- chunks 1,2: gh over hprev, K-range [split*128, +128)
    for (int c = 0; c < 2; c++) {
        const int k0 = split * 128 + c * 64;
        #pragma unroll
        for (int i = 0; i < 32; i++) {
            int idx = tid + 128 * i;
            int k = idx & 63, b = idx >> 6;
            as_[k][b] = hprev[b * HDIM + k0 + k];
        }
        #pragma unroll
        for (int i = 0; i < 16; i++) {
            int idx = tid + 128 * i;
            int k = idx & 63, j = idx >> 6;
            ws_[k][j] = W_hh[(size_t)(j0 + j) * HDIM + k0 + k];
        }
        __syncthreads();
        #pragma unroll 4
        for (int k = 0; k < 64; k++) {
            float a0 = as_[k][tb], a1 = as_[k][tb + 16], a2 = as_[k][tb + 32], a3 = as_[k][tb + 48];
            #pragma unroll
            for (int ji = 0; ji < 4; ji++) {
                float w = ws_[k][tj + 8 * ji];
                acch[ji * 4 + 0] += w * a0;
                acch[ji * 4 + 1] += w * a1;
                acch[ji * 4 + 2] += w * a2;
                acch[ji * 4 + 3] += w * a3;
            }
        }
        __syncthreads();
    }

    // ---------------- store partials
    const int sb = split * BATCH;
    #pragma unroll
    for (int ji = 0; ji < 4; ji++) {
        int j = j0 + tj + 8 * ji;
        #pragma unroll
        for (int bi = 0; bi < 4; bi++) {
            int b = tb + 16 * bi;
            g_gi_part[(size_t)(sb + b) * G3 + j] = acci[ji * 4 + bi];
            g_gh_part[(size_t)(sb + b) * G3 + j] = acch[ji * 4 + bi];
        }
    }
}

// ---------------------------------------------------------------------------
// Kernel 2: combine split-K partials, gate math, h_new, argmax-slot reset.
// grid = 64 (b), block = 512 (j).
// ---------------------------------------------------------------------------
__global__ __launch_bounds__(512) void gru_combine_kernel(
    int s,
    const float* __restrict__ h0,
    const float* __restrict__ b_ih,
    const float* __restrict__ b_hh)
{
    const int b = blockIdx.x;
    const int j = threadIdx.x;

    float gir = 0.f, giz = 0.f, gin = 0.f, ghr = 0.f, ghz = 0.f, ghn = 0.f;
    #pragma unroll
    for (int sp = 0; sp < 4; sp++) {
        const float* gi = g_gi_part + (size_t)(sp * BATCH + b) * G3;
        const float* gh = g_gh_part + (size_t)(sp * BATCH + b) * G3;
        gir += gi[j];            giz += gi[j + HDIM];     gin += gi[j + 2 * HDIM];
        ghr += gh[j];            ghz += gh[j + HDIM];     ghn += gh[j + 2 * HDIM];
    }
    gir += b_ih[j];  giz += b_ih[j + HDIM];  gin += b_ih[j + 2 * HDIM];
    ghr += b_hh[j];  ghz += b_hh[j + HDIM];  ghn += b_hh[j + 2 * HDIM];

    float r = 1.f / (1.f + expf(-(gir + ghr)));
    float z = 1.f / (1.f + expf(-(giz + ghz)));
    float n = tanhf(gin + r * ghn);

    float hold = (s == 0) ? h0[b * HDIM + j] : g_h[b * HDIM + j];
    g_h[b * HDIM + j] = (1.f - z) * n + z * hold;

    // reset argmax slots before this step's classifier runs
    if (b == 0 && j < BATCH) g_amax[j * 32] = 0ull;
}

// ---------------------------------------------------------------------------
// Kernel 3: classifier logits = h @ Wc^T + bc, write out, fused argmax.
// grid = 393 v-tiles of 128, block = 128 threads, 3 blocks/SM (one wave).
// Thread (tv=tid&15, tb=tid>>4) computes 8v x 8b. The 8 b's are processed as
// 4 packed f32x2 pairs via PTX fma.rn.f32x2 (SASS FFMA2): 2 fp32 FMAs per
// issue slot, halving the FMA-issue bound. Wc values are pre-duplicated into
// a float2 smem tile so the inner loop is pure LDS64 + FFMA2.
// Per-element accumulation order is identical to the scalar version ->
// bit-identical logits and argmax.
// ---------------------------------------------------------------------------
__device__ __forceinline__ unsigned int order_enc(float f) {
    unsigned int u = __float_as_uint(f);
    return (u & 0x80000000u) ? ~u : (u | 0x80000000u);
}

__global__ __launch_bounds__(128, 3) void cls_kernel(
    int s,
    const float* __restrict__ Wc,
    const float* __restrict__ bc,
    float* __restrict__ out)
{
    __shared__ __align__(16) unsigned long long ws2_[16][128]; // [k][v], (w,w) duplicated
    __shared__ __align__(16) float hs_[16][64];                // [k][b]

    const int tid = threadIdx.x;
    const int tv  = tid & 15;
    const int tb  = tid >> 4;       // 0..7
    const int vg  = blockIdx.x * 128;

    unsigned long long acc2[8][4];  // [vi][b-pair], packed f32x2
    #pragma unroll
    for (int vi = 0; vi < 8; vi++)
        #pragma unroll
        for (int p = 0; p < 4; p++) acc2[vi][p] = 0ull;

    for (int kc = 0; kc < HDIM / 16; kc++) {
        const int k0 = kc * 16;
        // Wc tile: transpose + duplicate each value into both f32x2 lanes
        #pragma unroll
        for (int i = 0; i < 4; i++) {
            int idx = tid + 128 * i;
            int v = idx >> 2, kq = idx & 3;
            int vglob = vg + v;
            float4 w = (vglob < VOCAB)
                ? *(const float4*)(Wc + (size_t)vglob * HDIM + k0 + 4 * kq)
                : make_float4(0.f, 0.f, 0.f, 0.f);
            unsigned int ux = __float_as_uint(w.x), uy = __float_as_uint(w.y);
            unsigned int uz = __float_as_uint(w.z), uw = __float_as_uint(w.w);
            ws2_[4 * kq + 0][v] = ux | ((unsigned long long)ux << 32);
            ws2_[4 * kq + 1][v] = uy | ((unsigned long long)uy << 32);
            ws2_[4 * kq + 2][v] = uz | ((unsigned long long)uz << 32);
            ws2_[4 * kq + 3][v] = uw | ((unsigned long long)uw << 32);
        }
        // h tile
        #pragma unroll
        for (int i = 0; i < 8; i++) {
            int idx = tid + 128 * i;
            int k = idx & 15, b = idx >> 4;
            hs_[k][b] = g_h[b * HDIM + k0 + k];
        }
        __syncthreads();

        #pragma unroll
        for (int k = 0; k < 16; k++) {
            unsigned long long h2[4], w2[8];
            const unsigned long long* hp =
                (const unsigned long long*)&hs_[k][8 * tb];
            #pragma unroll
            for (int p = 0; p < 4; p++) h2[p] = hp[p];          // (b=2p, b=2p+1)
            #pragma unroll
            for (int vi = 0; vi < 8; vi++) w2[vi] = ws2_[k][tv + 16 * vi];
            #pragma unroll
            for (int vi = 0; vi < 8; vi++)
                #pragma unroll
                for (int p = 0; p < 4; p++)
                    asm("fma.rn.f32x2 %0, %1, %2, %0;"
                        : "+l"(acc2[vi][p]) : "l"(w2[vi]), "l"(h2[p]));
        }
        __syncthreads();
    }

    // epilogue: bias, store, argmax
    unsigned long long key[8];
    #pragma unroll
    for (int bi = 0; bi < 8; bi++) key[bi] = 0ull;

    #pragma unroll
    for (int vi = 0; vi < 8; vi++) {
        int v = vg + tv + 16 * vi;
        if (v < VOCAB) {
            float bcv = bc[v];
            #pragma unroll
            for (int p = 0; p < 4; p++) {
                float accl = __uint_as_float((unsigned int)(acc2[vi][p]));
                float acch = __uint_as_float((unsigned int)(acc2[vi][p] >> 32));
                #pragma unroll
                for (int half = 0; half < 2; half++) {
                    float logit = (half ? acch : accl) + bcv;
                    int bi = 2 * p + half;
                    int b = 8 * tb + bi;
                    out[(size_t)(s * BATCH + b) * VOCAB + v] = logit;
                    unsigned long long k2 =
                        ((unsigned long long)order_enc(logit) << 32) |
                        (unsigned long long)(unsigned int)(~v);
                    if (k2 > key[bi]) key[bi] = k2;
                }
            }
        }
    }

    // reduce across the 16 tv lanes (shfl stays inside each 16-lane half)
    #pragma unroll
    for (int bi = 0; bi < 8; bi++) {
        unsigned long long k2 = key[bi];
        #pragma unroll
        for (int d = 8; d > 0; d >>= 1) {
            unsigned long long o = __shfl_xor_sync(0xFFFFFFFFu, k2, d);
            if (o > k2) k2 = o;
        }
        key[bi] = k2;
    }
    if (tv == 0) {
        #pragma unroll
        for (int bi = 0; bi < 8; bi++)
            atomicMax(&g_amax[(8 * tb + bi) * 32], key[bi]);
    }
}

// ---------------------------------------------------------------------------
// Launch: 64 steps x (gru_gemm -> gru_combine -> classifier), one stream,
// whole sequence captured into one graph.
// ---------------------------------------------------------------------------
extern "C" void kernel_launch(void* const* d_in, const int* in_sizes, int n_in,
                              void* d_out, int out_size)
{
    const float* h0   = (const float*)d_in[0];
    const float* emb  = (const float*)d_in[1];
    const float* W_ih = (const float*)d_in[2];
    const float* W_hh = (const float*)d_in[3];
    const float* b_ih = (const float*)d_in[4];
    const float* b_hh = (const float*)d_in[5];
    const float* Wc   = (const float*)d_in[6];
    const float* bc   = (const float*)d_in[7];
    float* out = (float*)d_out;

    const int n_vtiles = (VOCAB + 127) / 128;  // 393

    for (int s = 0; s < LSEQ; s++) {
        gru_gemm_kernel<<<dim3(48, 4), 128>>>(s, h0, emb, W_ih, W_hh);
        gru_combine_kernel<<<BATCH, 512>>>(s, h0, b_ih, b_hh);
        cls_kernel<<<n_vtiles, 128>>>(s, Wc, bc, out);
    }
}

// round 14
// speedup vs baseline: 1.5780x; 1.5780x over previous
#include <cuda_runtime.h>
#include <cuda_bf16.h>
#include <math.h>
#include <stdint.h>

#define VOCAB 50257
#define EDIM  256
#define HDIM  512
#define G3    1536
#define BATCH 64
#define LSEQ  64
#define SOS_TOK 2

// classifier tiling
#define NTILES 393                    // 128-row M tiles (393*128 = 50304, zero padded)
#define ROWAF  272                    // fp32 A row stride in smem (256B data + 16B pad)
#define AF_CHUNK_BYTES (128 * ROWAF)  // 34816
#define ROWB   144                    // bf16 B row stride (128B data + 16B pad)
#define B_CHUNK_BYTES (3 * 64 * ROWB) // 27648 (3 limbs x 64 batch rows)

// ---------------- persistent device state (no allocations allowed) ----------
__device__ float g_h[BATCH * HDIM];
__device__ float g_part[12 * BATCH * G3];
__device__ unsigned long long g_amax[BATCH * 32];
__device__ __align__(16) unsigned char g_Bimg[8 * B_CHUNK_BYTES];  // h limb images (~221KB)

// ---------------- helpers ---------------------------------------------------
__device__ __forceinline__ uint32_t smem_u32(const void* p) {
    uint32_t a;
    asm("{ .reg .u64 t; cvta.to.shared.u64 t, %1; cvt.u32.u64 %0, t; }" : "=r"(a) : "l"(p));
    return a;
}
__device__ __forceinline__ void cp16(uint32_t dst, const void* src) {
    asm volatile("cp.async.cg.shared.global [%0], [%1], 16;" :: "r"(dst), "l"(src));
}
#define CP_COMMIT() asm volatile("cp.async.commit_group;" ::: "memory")
#define CP_WAIT1()  asm volatile("cp.async.wait_group 1;" ::: "memory")

__device__ __forceinline__ void mma_bf16(float* c, const uint32_t* a, const uint32_t* b) {
    asm volatile(
        "mma.sync.aligned.m16n8k16.row.col.f32.bf16.bf16.f32 "
        "{%0,%1,%2,%3}, {%4,%5,%6,%7}, {%8,%9}, {%0,%1,%2,%3};"
        : "+f"(c[0]), "+f"(c[1]), "+f"(c[2]), "+f"(c[3])
        : "r"(a[0]), "r"(a[1]), "r"(a[2]), "r"(a[3]), "r"(b[0]), "r"(b[1]));
}

// split a float2 (f0 = lower/even k, f1 = upper/odd k) into 3 packed bf16x2 limbs
__device__ __forceinline__ void limb_split(float f0, float f1,
                                           uint32_t& hi, uint32_t& mi, uint32_t& lo) {
    uint32_t h;
    asm("cvt.rn.bf16x2.f32 %0, %1, %2;" : "=r"(h) : "f"(f1), "f"(f0));
    float h0 = __uint_as_float(h << 16);
    float h1 = __uint_as_float(h & 0xffff0000u);
    float r0 = f0 - h0, r1 = f1 - h1;
    uint32_t m;
    asm("cvt.rn.bf16x2.f32 %0, %1, %2;" : "=r"(m) : "f"(r1), "f"(r0));
    float m0 = __uint_as_float(m << 16);
    float m1 = __uint_as_float(m & 0xffff0000u);
    float s0 = r0 - m0, s1 = r1 - m1;
    uint32_t l;
    asm("cvt.rn.bf16x2.f32 %0, %1, %2;" : "=r"(l) : "f"(s1), "f"(s0));
    hi = h; mi = m; lo = l;
}

__device__ __forceinline__ unsigned int order_enc(float f) {
    unsigned int u = __float_as_uint(f);
    return (u & 0x80000000u) ? ~u : (u | 0x80000000u);
}

// ---------------------------------------------------------------------------
// Kernel 1: unified GRU GEMM, split-K = 12 chunks of 64 (0-3: gi, 4-11: gh).
// grid = (48, 12) = 576 blocks, 128 threads.
// ---------------------------------------------------------------------------
__global__ __launch_bounds__(128) void gru_gemm_kernel(
    int s,
    const float* __restrict__ h0,
    const float* __restrict__ emb,
    const float* __restrict__ W_ih,
    const float* __restrict__ W_hh)
{
    __shared__ int   stok[BATCH];
    __shared__ float as_[64][65];
    __shared__ float ws_[64][33];

    const int tid = threadIdx.x;
    const int jt  = blockIdx.x;
    const int sp  = blockIdx.y;
    const int j0  = jt * 32;
    const int tj  = tid & 7;
    const int tb  = tid >> 3;
    const bool is_gi = (sp < 4);
    const int k0 = is_gi ? sp * 64 : (sp - 4) * 64;

    if (is_gi && tid < BATCH) {
        int t;
        if (s == 0) t = SOS_TOK;
        else        t = (int)(~(unsigned int)(g_amax[tid * 32] & 0xFFFFFFFFull));
        stok[tid] = t;
    }
    if (is_gi) __syncthreads();

    const float* __restrict__ hprev = (s == 0) ? h0 : g_h;

    #pragma unroll
    for (int i = 0; i < 32; i++) {
        int idx = tid + 128 * i;
        int k = idx & 63, b = idx >> 6;
        as_[k][b] = is_gi ? emb[(size_t)stok[b] * EDIM + k0 + k]
                          : hprev[b * HDIM + k0 + k];
    }
    #pragma unroll
    for (int i = 0; i < 16; i++) {
        int idx = tid + 128 * i;
        int k = idx & 63, j = idx >> 6;
        ws_[k][j] = is_gi ? W_ih[(size_t)(j0 + j) * EDIM + k0 + k]
                          : W_hh[(size_t)(j0 + j) * HDIM + k0 + k];
    }
    __syncthreads();

    float acc[16];
    #pragma unroll
    for (int i = 0; i < 16; i++) acc[i] = 0.f;

    #pragma unroll 4
    for (int k = 0; k < 64; k++) {
        float a0 = as_[k][tb], a1 = as_[k][tb + 16], a2 = as_[k][tb + 32], a3 = as_[k][tb + 48];
        #pragma unroll
        for (int ji = 0; ji < 4; ji++) {
            float w = ws_[k][tj + 8 * ji];
            acc[ji * 4 + 0] += w * a0;
            acc[ji * 4 + 1] += w * a1;
            acc[ji * 4 + 2] += w * a2;
            acc[ji * 4 + 3] += w * a3;
        }
    }

    #pragma unroll
    for (int ji = 0; ji < 4; ji++) {
        int j = j0 + tj + 8 * ji;
        #pragma unroll
        for (int bi = 0; bi < 4; bi++) {
            int b = tb + 16 * bi;
            g_part[(size_t)(sp * BATCH + b) * G3 + j] = acc[ji * 4 + bi];
        }
    }
}

// ---------------------------------------------------------------------------
// Kernel 2: combine partials, gates, h_new; emit 3-limb bf16 h images;
// reset argmax slots. grid=64, block=512.
// ---------------------------------------------------------------------------
__global__ __launch_bounds__(512) void gru_combine_kernel(
    int s,
    const float* __restrict__ h0,
    const float* __restrict__ b_ih,
    const float* __restrict__ b_hh)
{
    const int b = blockIdx.x;
    const int j = threadIdx.x;

    float gir = 0.f, giz = 0.f, gin = 0.f, ghr = 0.f, ghz = 0.f, ghn = 0.f;
    #pragma unroll
    for (int sp = 0; sp < 4; sp++) {
        const float* p = g_part + (size_t)(sp * BATCH + b) * G3;
        gir += p[j]; giz += p[j + HDIM]; gin += p[j + 2 * HDIM];
    }
    #pragma unroll
    for (int sp = 4; sp < 12; sp++) {
        const float* p = g_part + (size_t)(sp * BATCH + b) * G3;
        ghr += p[j]; ghz += p[j + HDIM]; ghn += p[j + 2 * HDIM];
    }
    gir += b_ih[j];  giz += b_ih[j + HDIM];  gin += b_ih[j + 2 * HDIM];
    ghr += b_hh[j];  ghz += b_hh[j + HDIM];  ghn += b_hh[j + 2 * HDIM];

    float r = 1.f / (1.f + expf(-(gir + ghr)));
    float z = 1.f / (1.f + expf(-(giz + ghz)));
    float n = tanhf(gin + r * ghn);

    float hold = (s == 0) ? h0[b * HDIM + j] : g_h[b * HDIM + j];
    float hn = (1.f - z) * n + z * hold;
    g_h[b * HDIM + j] = hn;

    __nv_bfloat16 hi = __float2bfloat16(hn);
    float rem = hn - __bfloat162float(hi);
    __nv_bfloat16 mid = __float2bfloat16(rem);
    float rem2 = rem - __bfloat162float(mid);
    __nv_bfloat16 lo = __float2bfloat16(rem2);

    int kc = j >> 6, kk = j & 63;
    size_t base = (size_t)kc * B_CHUNK_BYTES + (size_t)b * ROWB + kk * 2;
    *(__nv_bfloat16*)(g_Bimg + base + 0 * 64 * ROWB) = hi;
    *(__nv_bfloat16*)(g_Bimg + base + 1 * 64 * ROWB) = mid;
    *(__nv_bfloat16*)(g_Bimg + base + 2 * 64 * ROWB) = lo;

    if (b == 0 && j < BATCH) g_amax[j * 32] = 0ull;
}

// ---------------------------------------------------------------------------
// Kernel 3: classifier on mma.sync bf16 tensor cores, register-side limb split.
// CTA: 128 vocab rows x N=64, 8 warps (warp tile 32x32).
// Per kc chunk (8 of 64 k): cp.async fp32 Wc tile + bf16 h limb images
// (double-buffered); per k16: load fp32 A float2 fragments, split into
// hi/mid/lo bf16 limbs in registers, and issue the 6 limb products
// {HH, HM, HL, MH, MM, LH} into one fp32 accumulator set.
// ---------------------------------------------------------------------------
#define SM_A 0
#define SM_B (2 * AF_CHUNK_BYTES)
#define CLS_SMEM (2 * AF_CHUNK_BYTES + 2 * B_CHUNK_BYTES)   // 124928

__global__ __launch_bounds__(256, 1)
void cls_kernel(int s, const float* __restrict__ Wc, const float* __restrict__ bc,
                float* __restrict__ out)
{
    extern __shared__ __align__(128) unsigned char smem[];
    __shared__ unsigned long long skey[BATCH];

    const uint32_t sb = smem_u32(smem);
    const int tid  = threadIdx.x;
    const int wid  = tid >> 5;
    const int lane = tid & 31;
    const int g    = lane >> 2;
    const int tig  = lane & 3;
    const int mrow0 = (wid & 3) * 32;
    const int ncol0 = (wid >> 2) * 32;
    const int tile = blockIdx.x;

    if (tid < BATCH) skey[tid] = 0ull;

    const float* Wbase = Wc + (size_t)tile * 128 * HDIM;

    // A chunk: 128 rows x 16 segments of 16B (fp32), predicated on vocab bound
    #define ISSUE_AF(kc_, p_) do {                                              \
        uint32_t dst = sb + SM_A + (p_) * AF_CHUNK_BYTES;                       \
        _Pragma("unroll")                                                       \
        for (int q = 0; q < 8; q++) {                                           \
            int idx = tid + 256 * q;                                            \
            int row = idx >> 4, seg = idx & 15;                                 \
            if (tile * 128 + row < VOCAB)                                       \
                cp16(dst + row * ROWAF + seg * 16,                              \
                     Wbase + (size_t)row * HDIM + (kc_) * 64 + seg * 4);        \
        }                                                                       \
    } while (0)

    #define ISSUE_B(kc_, p_) do {                                               \
        const unsigned char* src = g_Bimg + (size_t)(kc_) * B_CHUNK_BYTES;      \
        uint32_t dst = sb + SM_B + (p_) * B_CHUNK_BYTES;                        \
        _Pragma("unroll")                                                       \
        for (int q = 0; q < 6; q++)                                             \
            cp16(dst + (tid + 256 * q) * 16, src + (size_t)(tid + 256 * q) * 16); \
        if (tid < 192) cp16(dst + (1536 + tid) * 16, src + (size_t)(1536 + tid) * 16); \
    } while (0)

    float acc[2][4][4];
    #pragma unroll
    for (int mf = 0; mf < 2; mf++)
        #pragma unroll
        for (int nf = 0; nf < 4; nf++)
            #pragma unroll
            for (int i = 0; i < 4; i++) acc[mf][nf][i] = 0.f;

    ISSUE_B(0, 0);
    ISSUE_AF(0, 0);
    CP_COMMIT();

    for (int kc = 0; kc < 8; kc++) {
        const int nk = kc + 1;
        if (nk < 8) { ISSUE_B(nk, nk & 1); ISSUE_AF(nk, nk & 1); }
        CP_COMMIT();
        CP_WAIT1();
        __syncthreads();

        const uint32_t aOff = SM_A + (kc & 1) * AF_CHUNK_BYTES;
        const uint32_t bOff = SM_B + (kc & 1) * B_CHUNK_BYTES;

        #pragma unroll
        for (int kk16 = 0; kk16 < 4; kk16++) {
            const uint32_t kb = kk16 * 64 + tig * 8;   // fp32 bytes within row

            uint32_t aH[2][4], aM[2][4], aL[2][4];
            #pragma unroll
            for (int mf = 0; mf < 2; mf++) {
                uint32_t a0 = aOff + (mrow0 + mf * 16 + g) * ROWAF + kb;
                float2 p0 = *(const float2*)(smem + a0);
                float2 p1 = *(const float2*)(smem + a0 + 8 * ROWAF);
                float2 p2 = *(const float2*)(smem + a0 + 32);
                float2 p3 = *(const float2*)(smem + a0 + 8 * ROWAF + 32);
                limb_split(p0.x, p0.y, aH[mf][0], aM[mf][0], aL[mf][0]);
                limb_split(p1.x, p1.y, aH[mf][1], aM[mf][1], aL[mf][1]);
                limb_split(p2.x, p2.y, aH[mf][2], aM[mf][2], aL[mf][2]);
                limb_split(p3.x, p3.y, aH[mf][3], aM[mf][3], aL[mf][3]);
            }

            uint32_t bF[3][4][2];
            #pragma unroll
            for (int bsel = 0; bsel < 3; bsel++) {
                const uint32_t bB = bOff + bsel * (64 * ROWB);
                #pragma unroll
                for (int nf = 0; nf < 4; nf++) {
                    uint32_t b0 = bB + (ncol0 + nf * 8 + g) * ROWB + kk16 * 32 + tig * 4;
                    bF[bsel][nf][0] = *(const uint32_t*)(smem + b0);
                    bF[bsel][nf][1] = *(const uint32_t*)(smem + b0 + 16);
                }
            }

            #pragma unroll
            for (int mf = 0; mf < 2; mf++)
                #pragma unroll
                for (int nf = 0; nf < 4; nf++) {
                    mma_bf16(acc[mf][nf], aH[mf], bF[0][nf]);   // H*H
                    mma_bf16(acc[mf][nf], aH[mf], bF[1][nf]);   // H*M
                    mma_bf16(acc[mf][nf], aH[mf], bF[2][nf]);   // H*L
                    mma_bf16(acc[mf][nf], aM[mf], bF[0][nf]);   // M*H
                    mma_bf16(acc[mf][nf], aM[mf], bF[1][nf]);   // M*M
                    mma_bf16(acc[mf][nf], aL[mf], bF[0][nf]);   // L*H
                }
        }
        __syncthreads();
    }

    // -------- epilogue: stage logits in smem [64 b][132 v-stride] -----------
    float* ls = (float*)smem;
    #pragma unroll
    for (int mf = 0; mf < 2; mf++) {
        #pragma unroll
        for (int nf = 0; nf < 4; nf++) {
            int v0 = mrow0 + mf * 16 + g;
            int b0 = ncol0 + nf * 8 + 2 * tig;
            ls[(b0)     * 132 + v0]     = acc[mf][nf][0];
            ls[(b0 + 1) * 132 + v0]     = acc[mf][nf][1];
            ls[(b0)     * 132 + v0 + 8] = acc[mf][nf][2];
            ls[(b0 + 1) * 132 + v0 + 8] = acc[mf][nf][3];
        }
    }
    __syncthreads();

    const int vg = tile * 128;
    #pragma unroll 4
    for (int it = 0; it < 32; it++) {
        int b = it * 2 + (tid >> 7);
        int v = tid & 127;
        int vglob = vg + v;
        unsigned long long key = 0ull;
        if (vglob < VOCAB) {
            float logit = ls[b * 132 + v] + bc[vglob];
            out[(size_t)(s * BATCH + b) * VOCAB + vglob] = logit;
            key = ((unsigned long long)order_enc(logit) << 32) |
                  (unsigned long long)(unsigned int)(~vglob);
        }
        #pragma unroll
        for (int d = 16; d > 0; d >>= 1) {
            unsigned long long o = __shfl_xor_sync(0xFFFFFFFFu, key, d);
            if (o > key) key = o;
        }
        if (lane == 0 && key) atomicMax(&skey[b], key);
    }
    __syncthreads();
    if (tid < BATCH && skey[tid]) atomicMax(&g_amax[tid * 32], skey[tid]);
}

// ---------------------------------------------------------------------------
extern "C" void kernel_launch(void* const* d_in, const int* in_sizes, int n_in,
                              void* d_out, int out_size)
{
    const float* h0   = (const float*)d_in[0];
    const float* emb  = (const float*)d_in[1];
    const float* W_ih = (const float*)d_in[2];
    const float* W_hh = (const float*)d_in[3];
    const float* b_ih = (const float*)d_in[4];
    const float* b_hh = (const float*)d_in[5];
    const float* Wc   = (const float*)d_in[6];
    const float* bc   = (const float*)d_in[7];
    float* out = (float*)d_out;

    cudaFuncSetAttribute(cls_kernel, cudaFuncAttributeMaxDynamicSharedMemorySize, CLS_SMEM);

    for (int s = 0; s < LSEQ; s++) {
        gru_gemm_kernel<<<dim3(48, 12), 128>>>(s, h0, emb, W_ih, W_hh);
        gru_combine_kernel<<<BATCH, 512>>>(s, h0, b_ih, b_hh);
        cls_kernel<<<NTILES, 256, CLS_SMEM>>>(s, Wc, bc, out);
    }
}

// round 16
// speedup vs baseline: 2.3246x; 1.4732x over previous
#include <cuda_runtime.h>
#include <cuda_fp16.h>
#include <math.h>
#include <stdint.h>

#define VOCAB 50257
#define EDIM  256
#define HDIM  512
#define G3    1536
#define BATCH 64
#define LSEQ  64
#define SOS_TOK 2

// classifier tiling
#define NTILES 393                    // 128-row M tiles (393*128 = 50304, zero padded)
#define ROWAF  272                    // fp32 A row stride in smem (256B data + 16B pad)
#define AF_CHUNK_BYTES (128 * ROWAF)  // 34816
#define ROWB   144                    // fp16 B row stride (128B data + 16B pad)
#define B_CHUNK_BYTES (2 * 64 * ROWB) // 18432 (2 limbs x 64 batch rows)
#define INV2048 4.8828125e-4f

// GRU split-K
#define NSPLIT 24                     // 8 chunks of 32 (gi) + 16 chunks of 32 (gh)

// ---------------- persistent device state (no allocations allowed) ----------
__device__ float g_h[BATCH * HDIM];
__device__ float g_part[NSPLIT * BATCH * G3];
__device__ unsigned long long g_amax[BATCH * 32];
__device__ __align__(16) unsigned char g_Bimg[8 * B_CHUNK_BYTES];  // h limb images (~147KB)

// ---------------- helpers ---------------------------------------------------
__device__ __forceinline__ uint32_t smem_u32(const void* p) {
    uint32_t a;
    asm("{ .reg .u64 t; cvta.to.shared.u64 t, %1; cvt.u32.u64 %0, t; }" : "=r"(a) : "l"(p));
    return a;
}
__device__ __forceinline__ void cp16(uint32_t dst, const void* src) {
    asm volatile("cp.async.cg.shared.global [%0], [%1], 16;" :: "r"(dst), "l"(src));
}
#define CP_COMMIT() asm volatile("cp.async.commit_group;" ::: "memory")
#define CP_WAIT1()  asm volatile("cp.async.wait_group 1;" ::: "memory")

__device__ __forceinline__ void mma_f16(float* c, const uint32_t* a, const uint32_t* b) {
    asm volatile(
        "mma.sync.aligned.m16n8k16.row.col.f32.f16.f16.f32 "
        "{%0,%1,%2,%3}, {%4,%5,%6,%7}, {%8,%9}, {%0,%1,%2,%3};"
        : "+f"(c[0]), "+f"(c[1]), "+f"(c[2]), "+f"(c[3])
        : "r"(a[0]), "r"(a[1]), "r"(a[2]), "r"(a[3]), "r"(b[0]), "r"(b[1]));
}

// split a float2 into 2 packed f16x2 limbs: w ~= W0 + W1 * 2^-11
__device__ __forceinline__ void split_f16(float f0, float f1, uint32_t& w0, uint32_t& w1) {
    uint32_t h;
    asm("cvt.rn.f16x2.f32 %0, %1, %2;" : "=r"(h) : "f"(f1), "f"(f0));
    float g0, g1;
    asm("{ .reg .f16 lo, hi; mov.b32 {lo, hi}, %2; cvt.f32.f16 %0, lo; cvt.f32.f16 %1, hi; }"
        : "=f"(g0), "=f"(g1) : "r"(h));
    float r0 = (f0 - g0) * 2048.f;
    float r1 = (f1 - g1) * 2048.f;
    asm("cvt.rn.f16x2.f32 %0, %1, %2;" : "=r"(w1) : "f"(r1), "f"(r0));
    w0 = h;
}

__device__ __forceinline__ unsigned int order_enc(float f) {
    unsigned int u = __float_as_uint(f);
    return (u & 0x80000000u) ? ~u : (u | 0x80000000u);
}

// ---------------------------------------------------------------------------
// Kernel 1: unified GRU GEMM, split-K = 24 chunks of 32 (0-7: gi, 8-23: gh).
// grid = (48, 24) = 1152 blocks, 128 threads.
// ---------------------------------------------------------------------------
__global__ __launch_bounds__(128) void gru_gemm_kernel(
    int s,
    const float* __restrict__ h0,
    const float* __restrict__ emb,
    const float* __restrict__ W_ih,
    const float* __restrict__ W_hh)
{
    __shared__ int   stok[BATCH];
    __shared__ float as_[32][65];
    __shared__ float ws_[32][33];

    const int tid = threadIdx.x;
    const int jt  = blockIdx.x;
    const int sp  = blockIdx.y;          // 0..23
    const int j0  = jt * 32;
    const int tj  = tid & 7;
    const int tb  = tid >> 3;
    const bool is_gi = (sp < 8);
    const int k0 = is_gi ? sp * 32 : (sp - 8) * 32;

    if (is_gi && tid < BATCH) {
        int t;
        if (s == 0) t = SOS_TOK;
        else        t = (int)(~(unsigned int)(g_amax[tid * 32] & 0xFFFFFFFFull));
        stok[tid] = t;
    }
    if (is_gi) __syncthreads();

    const float* __restrict__ hprev = (s == 0) ? h0 : g_h;

    #pragma unroll
    for (int i = 0; i < 16; i++) {
        int idx = tid + 128 * i;
        int k = idx & 31, b = idx >> 5;
        as_[k][b] = is_gi ? emb[(size_t)stok[b] * EDIM + k0 + k]
                          : hprev[b * HDIM + k0 + k];
    }
    #pragma unroll
    for (int i = 0; i < 8; i++) {
        int idx = tid + 128 * i;
        int k = idx & 31, j = idx >> 5;
        ws_[k][j] = is_gi ? W_ih[(size_t)(j0 + j) * EDIM + k0 + k]
                          : W_hh[(size_t)(j0 + j) * HDIM + k0 + k];
    }
    __syncthreads();

    float acc[16];
    #pragma unroll
    for (int i = 0; i < 16; i++) acc[i] = 0.f;

    #pragma unroll 4
    for (int k = 0; k < 32; k++) {
        float a0 = as_[k][tb], a1 = as_[k][tb + 16], a2 = as_[k][tb + 32], a3 = as_[k][tb + 48];
        #pragma unroll
        for (int ji = 0; ji < 4; ji++) {
            float w = ws_[k][tj + 8 * ji];
            acc[ji * 4 + 0] += w * a0;
            acc[ji * 4 + 1] += w * a1;
            acc[ji * 4 + 2] += w * a2;
            acc[ji * 4 + 3] += w * a3;
        }
    }

    #pragma unroll
    for (int ji = 0; ji < 4; ji++) {
        int j = j0 + tj + 8 * ji;
        #pragma unroll
        for (int bi = 0; bi < 4; bi++) {
            int b = tb + 16 * bi;
            g_part[(size_t)(sp * BATCH + b) * G3 + j] = acc[ji * 4 + bi];
        }
    }
}

// ---------------------------------------------------------------------------
// Kernel 2: combine partials, gates, h_new; emit 2-limb fp16 h images;
// reset argmax slots. grid=64, block=512.
// ---------------------------------------------------------------------------
__global__ __launch_bounds__(512) void gru_combine_kernel(
    int s,
    const float* __restrict__ h0,
    const float* __restrict__ b_ih,
    const float* __restrict__ b_hh)
{
    const int b = blockIdx.x;
    const int j = threadIdx.x;

    float gir = 0.f, giz = 0.f, gin = 0.f, ghr = 0.f, ghz = 0.f, ghn = 0.f;
    #pragma unroll
    for (int sp = 0; sp < 8; sp++) {
        const float* p = g_part + (size_t)(sp * BATCH + b) * G3;
        gir += p[j]; giz += p[j + HDIM]; gin += p[j + 2 * HDIM];
    }
    #pragma unroll
    for (int sp = 8; sp < 24; sp++) {
        const float* p = g_part + (size_t)(sp * BATCH + b) * G3;
        ghr += p[j]; ghz += p[j + HDIM]; ghn += p[j + 2 * HDIM];
    }
    gir += b_ih[j];  giz += b_ih[j + HDIM];  gin += b_ih[j + 2 * HDIM];
    ghr += b_hh[j];  ghz += b_hh[j + HDIM];  ghn += b_hh[j + 2 * HDIM];

    float r = 1.f / (1.f + expf(-(gir + ghr)));
    float z = 1.f / (1.f + expf(-(giz + ghz)));
    float n = tanhf(gin + r * ghn);

    float hold = (s == 0) ? h0[b * HDIM + j] : g_h[b * HDIM + j];
    float hn = (1.f - z) * n + z * hold;
    g_h[b * HDIM + j] = hn;

    // 2-limb fp16 split: hn ~= H0 + H1 * 2^-11
    __half H0 = __float2half_rn(hn);
    float rem = (hn - __half2float(H0)) * 2048.f;
    __half H1 = __float2half_rn(rem);

    int kc = j >> 6, kk = j & 63;
    size_t base = (size_t)kc * B_CHUNK_BYTES + (size_t)b * ROWB + kk * 2;
    *(__half*)(g_Bimg + base + 0 * 64 * ROWB) = H0;
    *(__half*)(g_Bimg + base + 1 * 64 * ROWB) = H1;

    if (b == 0 && j < BATCH) g_amax[j * 32] = 0ull;
}

// ---------------------------------------------------------------------------
// Kernel 3: classifier on mma.sync fp16 tensor cores, register-side 2-limb
// split. CTA: 128 vocab rows x N=64, 8 warps (warp tile 32x32), occ 2.
// Per kc chunk: cp.async fp32 Wc tile + fp16 h limb images (double-buffered);
// per k16: load fp32 A float2 fragments, split into W0/W1 fp16 limbs, then
// 3 MMAs: accA += W0*H0;  accB += W0*H1;  accB += W1*H0.
// logit = accA + accB * 2^-11.
// ---------------------------------------------------------------------------
#define SM_A 0
#define SM_B (2 * AF_CHUNK_BYTES)
#define CLS_SMEM (2 * AF_CHUNK_BYTES + 2 * B_CHUNK_BYTES)   // 106496

__global__ __launch_bounds__(256, 2)
void cls_kernel(int s, const float* __restrict__ Wc, const float* __restrict__ bc,
                float* __restrict__ out)
{
    extern __shared__ __align__(128) unsigned char smem[];
    __shared__ unsigned long long skey[BATCH];

    const uint32_t sb = smem_u32(smem);
    const int tid  = threadIdx.x;
    const int wid  = tid >> 5;
    const int lane = tid & 31;
    const int g    = lane >> 2;
    const int tig  = lane & 3;
    const int mrow0 = (wid & 3) * 32;
    const int ncol0 = (wid >> 2) * 32;
    const int tile = blockIdx.x;

    if (tid < BATCH) skey[tid] = 0ull;

    const float* Wbase = Wc + (size_t)tile * 128 * HDIM;

    #define ISSUE_AF(kc_, p_) do {                                              \
        uint32_t dst = sb + SM_A + (p_) * AF_CHUNK_BYTES;                       \
        _Pragma("unroll")                                                       \
        for (int q = 0; q < 8; q++) {                                           \
            int idx = tid + 256 * q;                                            \
            int row = idx >> 4, seg = idx & 15;                                 \
            if (tile * 128 + row < VOCAB)                                       \
                cp16(dst + row * ROWAF + seg * 16,                              \
                     Wbase + (size_t)row * HDIM + (kc_) * 64 + seg * 4);        \
        }                                                                       \
    } while (0)

    #define ISSUE_B(kc_, p_) do {                                               \
        const unsigned char* src = g_Bimg + (size_t)(kc_) * B_CHUNK_BYTES;      \
        uint32_t dst = sb + SM_B + (p_) * B_CHUNK_BYTES;                        \
        _Pragma("unroll")                                                       \
        for (int q = 0; q < 4; q++)                                             \
            cp16(dst + (tid + 256 * q) * 16, src + (size_t)(tid + 256 * q) * 16); \
        if (tid < 128) cp16(dst + (1024 + tid) * 16, src + (size_t)(1024 + tid) * 16); \
    } while (0)

    float accA[2][4][4], accB[2][4][4];
    #pragma unroll
    for (int mf = 0; mf < 2; mf++)
        #pragma unroll
        for (int nf = 0; nf < 4; nf++)
            #pragma unroll
            for (int i = 0; i < 4; i++) { accA[mf][nf][i] = 0.f; accB[mf][nf][i] = 0.f; }

    ISSUE_B(0, 0);
    ISSUE_AF(0, 0);
    CP_COMMIT();

    for (int kc = 0; kc < 8; kc++) {
        const int nk = kc + 1;
        if (nk < 8) { ISSUE_B(nk, nk & 1); ISSUE_AF(nk, nk & 1); }
        CP_COMMIT();
        CP_WAIT1();
        __syncthreads();

        const uint32_t aOff = SM_A + (kc & 1) * AF_CHUNK_BYTES;
        const uint32_t bOff = SM_B + (kc & 1) * B_CHUNK_BYTES;

        #pragma unroll
        for (int kk16 = 0; kk16 < 4; kk16++) {
            const uint32_t kb = kk16 * 64 + tig * 8;   // fp32 bytes within row

            uint32_t a0r[2][4], a1r[2][4];
            #pragma unroll
            for (int mf = 0; mf < 2; mf++) {
                uint32_t a0 = aOff + (mrow0 + mf * 16 + g) * ROWAF + kb;
                float2 p0 = *(const float2*)(smem + a0);
                float2 p1 = *(const float2*)(smem + a0 + 8 * ROWAF);
                float2 p2 = *(const float2*)(smem + a0 + 32);
                float2 p3 = *(const float2*)(smem + a0 + 8 * ROWAF + 32);
                split_f16(p0.x, p0.y, a0r[mf][0], a1r[mf][0]);
                split_f16(p1.x, p1.y, a0r[mf][1], a1r[mf][1]);
                split_f16(p2.x, p2.y, a0r[mf][2], a1r[mf][2]);
                split_f16(p3.x, p3.y, a0r[mf][3], a1r[mf][3]);
            }

            uint32_t bF[2][4][2];
            #pragma unroll
            for (int bsel = 0; bsel < 2; bsel++) {
                const uint32_t bB = bOff + bsel * (64 * ROWB);
                #pragma unroll
                for (int nf = 0; nf < 4; nf++) {
                    uint32_t b0 = bB + (ncol0 + nf * 8 + g) * ROWB + kk16 * 32 + tig * 4;
                    bF[bsel][nf][0] = *(const uint32_t*)(smem + b0);
                    bF[bsel][nf][1] = *(const uint32_t*)(smem + b0 + 16);
                }
            }

            #pragma unroll
            for (int mf = 0; mf < 2; mf++)
                #pragma unroll
                for (int nf = 0; nf < 4; nf++) {
                    mma_f16(accA[mf][nf], a0r[mf], bF[0][nf]);   // W0*H0
                    mma_f16(accB[mf][nf], a0r[mf], bF[1][nf]);   // W0*H1
                    mma_f16(accB[mf][nf], a1r[mf], bF[0][nf]);   // W1*H0
                }
        }
        __syncthreads();
    }

    // -------- epilogue: stage logits in smem [64 b][132 v-stride] -----------
    float* ls = (float*)smem;
    #pragma unroll
    for (int mf = 0; mf < 2; mf++) {
        #pragma unroll
        for (int nf = 0; nf < 4; nf++) {
            int v0 = mrow0 + mf * 16 + g;
            int b0 = ncol0 + nf * 8 + 2 * tig;
            ls[(b0)     * 132 + v0]     = accA[mf][nf][0] + accB[mf][nf][0] * INV2048;
            ls[(b0 + 1) * 132 + v0]     = accA[mf][nf][1] + accB[mf][nf][1] * INV2048;
            ls[(b0)     * 132 + v0 + 8] = accA[mf][nf][2] + accB[mf][nf][2] * INV2048;
            ls[(b0 + 1) * 132 + v0 + 8] = accA[mf][nf][3] + accB[mf][nf][3] * INV2048;
        }
    }
    __syncthreads();

    const int vg = tile * 128;
    #pragma unroll 4
    for (int it = 0; it < 32; it++) {
        int b = it * 2 + (tid >> 7);
        int v = tid & 127;
        int vglob = vg + v;
        unsigned long long key = 0ull;
        if (vglob < VOCAB) {
            float logit = ls[b * 132 + v] + bc[vglob];
            out[(size_t)(s * BATCH + b) * VOCAB + vglob] = logit;
            key = ((unsigned long long)order_enc(logit) << 32) |
                  (unsigned long long)(unsigned int)(~vglob);
        }
        #pragma unroll
        for (int d = 16; d > 0; d >>= 1) {
            unsigned long long o = __shfl_xor_sync(0xFFFFFFFFu, key, d);
            if (o > key) key = o;
        }
        if (lane == 0 && key) atomicMax(&skey[b], key);
    }
    __syncthreads();
    if (tid < BATCH && skey[tid]) atomicMax(&g_amax[tid * 32], skey[tid]);
}

// ---------------------------------------------------------------------------
extern "C" void kernel_launch(void* const* d_in, const int* in_sizes, int n_in,
                              void* d_out, int out_size)
{
    const float* h0   = (const float*)d_in[0];
    const float* emb  = (const float*)d_in[1];
    const float* W_ih = (const float*)d_in[2];
    const float* W_hh = (const float*)d_in[3];
    const float* b_ih = (const float*)d_in[4];
    const float* b_hh = (const float*)d_in[5];
    const float* Wc   = (const float*)d_in[6];
    const float* bc   = (const float*)d_in[7];
    float* out = (float*)d_out;

    cudaFuncSetAttribute(cls_kernel, cudaFuncAttributeMaxDynamicSharedMemorySize, CLS_SMEM);

    for (int s = 0; s < LSEQ; s++) {
        gru_gemm_kernel<<<dim3(48, 24), 128>>>(s, h0, emb, W_ih, W_hh);
        gru_combine_kernel<<<BATCH, 512>>>(s, h0, b_ih, b_hh);
        cls_kernel<<<NTILES, 256, CLS_SMEM>>>(s, Wc, bc, out);
    }
}